// round 4
// baseline (speedup 1.0000x reference)
#include <cuda_runtime.h>
#include <math.h>

#define OWN_DIM 7
#define INTR_DIM 5
#define N_HEADS 3
#define HEAD_DIM 5
#define N_INTR 256
#define HID 256
#define BATCH 16384
#define OBS_DIM 1287           // OWN_DIM + N_INTR*INTR_DIM
#define XDIM 22                // OWN_DIM + N_HEADS*HEAD_DIM
#define TR 32                  // rows per MLP block

typedef unsigned long long u64;

// transposed x buffer: [feature][row]  (1.44 MB device-global scratch)
__device__ float g_xT[XDIM * BATCH];

// ---- packed f32x2 helpers (sm_103a FFMA2 via PTX) ----
__device__ __forceinline__ u64 pack2(float lo, float hi){
    u64 r; asm("mov.b64 %0, {%1,%2};" : "=l"(r) : "f"(lo), "f"(hi)); return r;
}
__device__ __forceinline__ void unpack2(u64 v, float& lo, float& hi){
    asm("mov.b64 {%0,%1}, %2;" : "=f"(lo), "=f"(hi) : "l"(v));
}
__device__ __forceinline__ u64 ffma2(u64 a, u64 b, u64 c){
    u64 d; asm("fma.rn.f32x2 %0, %1, %2, %3;" : "=l"(d) : "l"(a), "l"(b), "l"(c)); return d;
}

// accurate-enough tanh (~1e-6 rel): tanh(x) = 1 - 2/(exp(2x)+1)
// __expf(+inf)->inf => 1-0 = 1 ; __expf(-big)->0 => 1-2 = -1 : no NaNs.
__device__ __forceinline__ float tanh_fast(float x){
    float e = __expf(2.0f * x);
    return 1.0f - __fdividef(2.0f, e + 1.0f);
}

// ============================================================
// Kernel 1: attention.  warp-per-row, 8 warps / block.
// ============================================================
__global__ void __launch_bounds__(256, 2)
attn_kernel(const float* __restrict__ obs,
            const float* __restrict__ Wq, const float* __restrict__ bq,
            const float* __restrict__ Wk, const float* __restrict__ bk,
            const float* __restrict__ Wv, const float* __restrict__ bv,
            const float* __restrict__ v_att, const float* __restrict__ temp)
{
    __shared__ float s_obs[8][OBS_DIM + 1];
    __shared__ float s_w[316];
    // smem weight layout offsets
    const int WQ = 0, BQ = 105, WK = 120, BK = 195, WV = 210, BV = 285, VA = 300, TT = 315;

    const int tid  = threadIdx.x;
    const int w    = tid >> 5;
    const int lane = tid & 31;

    // cooperative weight staging
    if (tid < 105)      s_w[WQ + tid]        = Wq[tid];
    else if (tid < 120) s_w[BQ + tid - 105]  = bq[tid - 105];
    else if (tid < 195) s_w[WK + tid - 120]  = Wk[tid - 120];
    else if (tid < 210) s_w[BK + tid - 195]  = bk[tid - 195];
    if (tid < 75)       s_w[WV + tid]        = Wv[tid];
    else if (tid < 90)  s_w[BV + tid - 75]   = bv[tid - 75];
    else if (tid < 105) s_w[VA + tid - 90]   = v_att[tid - 90];
    if (tid == 255)     s_w[TT]              = fabsf(temp[0]);

    // coalesced row staging (one warp per row)
    const int row = blockIdx.x * 8 + w;
    const float* gobs = obs + (size_t)row * OBS_DIM;
    for (int j = lane; j < OBS_DIM; j += 32) s_obs[w][j] = gobs[j];
    __syncthreads();

    const float* R = s_obs[w];

    // each lane owns 8 interaction items: n = lane + 32*t
    float xi[8][5];
    unsigned padmask = 0;
    #pragma unroll
    for (int t = 0; t < 8; t++){
        const float* p = R + OWN_DIM + 5 * (lane + 32 * t);
        float a = 0.f;
        #pragma unroll
        for (int i = 0; i < 5; i++){ xi[t][i] = p[i]; a += fabsf(xi[t][i]); }
        if (a < 1e-6f) padmask |= (1u << t);
    }

    // -------- pass 1: scores --------
    const float T = s_w[TT];
    float sc[3][8];
    #pragma unroll
    for (int h = 0; h < 3; h++){
        float qh[5], wk[25], bk5[5], va5[5];
        #pragma unroll
        for (int d = 0; d < 5; d++){
            float a = s_w[BQ + h*5 + d];
            #pragma unroll
            for (int o = 0; o < 7; o++) a += s_w[WQ + (h*5 + d)*7 + o] * R[o];
            qh[d]  = a;
            bk5[d] = s_w[BK + h*5 + d];
            va5[d] = s_w[VA + h*5 + d];
            #pragma unroll
            for (int i = 0; i < 5; i++) wk[d*5 + i] = s_w[WK + (h*5 + d)*5 + i];
        }
        #pragma unroll
        for (int t = 0; t < 8; t++){
            float s = 0.f;
            #pragma unroll
            for (int d = 0; d < 5; d++){
                float kv = bk5[d];
                #pragma unroll
                for (int i = 0; i < 5; i++) kv += wk[d*5 + i] * xi[t][i];
                float e = tanh_fast(qh[d] + kv);
                s += e * va5[d];
            }
            sc[h][t] = ((padmask >> t) & 1u) ? -INFINITY : s * T;
        }
    }

    // -------- softmax (per head, warp-wide over 256 items) --------
    float inv[3];
    #pragma unroll
    for (int h = 0; h < 3; h++){
        float m = -INFINITY;
        #pragma unroll
        for (int t = 0; t < 8; t++) m = fmaxf(m, sc[h][t]);
        #pragma unroll
        for (int off = 16; off; off >>= 1) m = fmaxf(m, __shfl_xor_sync(0xffffffffu, m, off));
        const bool ok = (m > -INFINITY);
        float l = 0.f;
        #pragma unroll
        for (int t = 0; t < 8; t++){
            float p = ok ? __expf(sc[h][t] - m) : 0.f;
            sc[h][t] = p;
            l += p;
        }
        #pragma unroll
        for (int off = 16; off; off >>= 1) l += __shfl_xor_sync(0xffffffffu, l, off);
        inv[h] = (l > 0.f) ? __fdividef(1.f, l) : 0.f;
    }

    // -------- pass 2: context = sum alpha * v --------
    float ctx[15];
    #pragma unroll
    for (int j = 0; j < 15; j++) ctx[j] = 0.f;
    #pragma unroll
    for (int h = 0; h < 3; h++){
        float wv[25], bv5[5];
        #pragma unroll
        for (int d = 0; d < 5; d++){
            bv5[d] = s_w[BV + h*5 + d];
            #pragma unroll
            for (int i = 0; i < 5; i++) wv[d*5 + i] = s_w[WV + (h*5 + d)*5 + i];
        }
        #pragma unroll
        for (int t = 0; t < 8; t++){
            float p = sc[h][t];
            #pragma unroll
            for (int d = 0; d < 5; d++){
                float vv = bv5[d];
                #pragma unroll
                for (int i = 0; i < 5; i++) vv += wv[d*5 + i] * xi[t][i];
                ctx[h*5 + d] += p * vv;
            }
        }
    }

    // warp-reduce the 15 context values, scale by 1/l
    #pragma unroll
    for (int j = 0; j < 15; j++){
        float c = ctx[j] * inv[j / 5];
        #pragma unroll
        for (int off = 16; off; off >>= 1) c += __shfl_xor_sync(0xffffffffu, c, off);
        ctx[j] = c;
    }

    if (lane == 0){
        #pragma unroll
        for (int o = 0; o < 7; o++)  g_xT[o * BATCH + row]        = R[o];
        #pragma unroll
        for (int j = 0; j < 15; j++) g_xT[(7 + j) * BATCH + row]  = ctx[j];
    }
}

// ============================================================
// Kernel 2: MLP.  256 threads (thread = hidden column), TR=32 rows/block.
// f32x2 packed math: each FFMA2 does 2 rows.
// ============================================================
__global__ void __launch_bounds__(256, 2)
mlp_kernel(const float* __restrict__ W1, const float* __restrict__ b1,
           const float* __restrict__ W2, const float* __restrict__ b2,
           const float* __restrict__ Wf, const float* __restrict__ bf,
           const float* __restrict__ log_std, float* __restrict__ out)
{
    extern __shared__ float sm[];
    float* xsT = sm;                       // [XDIM][TR]           704 floats
    float* h1T = sm + XDIM * TR;           // [HID][36] transposed (pad 36 => 16B-aligned rows)
    float* h2T = h1T + HID * 36;

    const int tid   = threadIdx.x;
    const int rbase = blockIdx.x * TR;

    // load x transposed tile (coalesced: 32 consecutive rows per feature)
    for (int idx = tid; idx < XDIM * TR; idx += 256)
        xsT[idx] = g_xT[(idx >> 5) * BATCH + rbase + (idx & 31)];
    __syncthreads();

    // ---- stage 1: h1 = lrelu(x @ W1 + b1) ----
    {
        float w1c[XDIM];
        #pragma unroll
        for (int i = 0; i < XDIM; i++) w1c[i] = W1[i * HID + tid];
        const float b = b1[tid];
        u64 acc[TR/2];
        const u64 bp = pack2(b, b);
        #pragma unroll
        for (int q = 0; q < TR/2; q++) acc[q] = bp;
        #pragma unroll
        for (int i = 0; i < XDIM; i++){
            const u64 wp = pack2(w1c[i], w1c[i]);
            const ulonglong2* xp = (const ulonglong2*)(xsT + i * TR);
            #pragma unroll
            for (int q = 0; q < TR/4; q++){
                ulonglong2 hh = xp[q];
                acc[2*q]   = ffma2(hh.x, wp, acc[2*q]);
                acc[2*q+1] = ffma2(hh.y, wp, acc[2*q+1]);
            }
        }
        #pragma unroll
        for (int q = 0; q < TR/2; q++){
            float a, c; unpack2(acc[q], a, c);
            a = fmaxf(a, 0.2f * a); c = fmaxf(c, 0.2f * c);
            *(u64*)(h1T + tid * 36 + 2 * q) = pack2(a, c);
        }
    }
    __syncthreads();

    // ---- stage 2: h2 = lrelu(h1 @ W2 + b2) ----
    {
        const float b = b2[tid];
        u64 acc[TR/2];
        const u64 bp = pack2(b, b);
        #pragma unroll
        for (int q = 0; q < TR/2; q++) acc[q] = bp;
        const float* w2c = W2 + tid;
        #pragma unroll 4
        for (int i = 0; i < HID; i++){
            const float wv = __ldg(w2c + i * HID);
            const u64 wp = pack2(wv, wv);
            const ulonglong2* hp = (const ulonglong2*)(h1T + i * 36);
            #pragma unroll
            for (int q = 0; q < TR/4; q++){
                ulonglong2 hh = hp[q];
                acc[2*q]   = ffma2(hh.x, wp, acc[2*q]);
                acc[2*q+1] = ffma2(hh.y, wp, acc[2*q+1]);
            }
        }
        #pragma unroll
        for (int q = 0; q < TR/2; q++){
            float a, c; unpack2(acc[q], a, c);
            a = fmaxf(a, 0.2f * a); c = fmaxf(c, 0.2f * c);
            *(u64*)(h2T + tid * 36 + 2 * q) = pack2(a, c);
        }
    }
    __syncthreads();

    // ---- stage 3: out = h2 @ Wf + bf ; append log_std ----
    if (tid < 64){
        const int r = tid >> 1, a = tid & 1;
        float acc = bf[a];
        #pragma unroll 8
        for (int j = 0; j < HID; j++)
            acc += h2T[j * 36 + r] * Wf[j * 2 + a];
        const int row = rbase + r;
        out[row * 4 + a]     = acc;
        out[row * 4 + 2 + a] = log_std[a];
    }
}

// ============================================================
extern "C" void kernel_launch(void* const* d_in, const int* in_sizes, int n_in,
                              void* d_out, int out_size)
{
    const float* obs     = (const float*)d_in[0];
    const float* Wq      = (const float*)d_in[1];
    const float* bq      = (const float*)d_in[2];
    const float* Wk      = (const float*)d_in[3];
    const float* bk      = (const float*)d_in[4];
    const float* Wv      = (const float*)d_in[5];
    const float* bv      = (const float*)d_in[6];
    const float* v_att   = (const float*)d_in[7];
    const float* temp    = (const float*)d_in[8];
    const float* W1      = (const float*)d_in[9];
    const float* b1      = (const float*)d_in[10];
    const float* W2      = (const float*)d_in[11];
    const float* b2      = (const float*)d_in[12];
    const float* Wf      = (const float*)d_in[13];
    const float* bf      = (const float*)d_in[14];
    const float* log_std = (const float*)d_in[15];

    attn_kernel<<<BATCH / 8, 256>>>(obs, Wq, bq, Wk, bk, Wv, bv, v_att, temp);

    const size_t smem = (size_t)(XDIM * TR + 2 * HID * 36) * sizeof(float);  // 76544 B
    cudaFuncSetAttribute(mlp_kernel, cudaFuncAttributeMaxDynamicSharedMemorySize, (int)smem);
    mlp_kernel<<<BATCH / TR, 256, smem>>>(W1, b1, W2, b2, Wf, bf, log_std, (float*)d_out);
}

// round 5
// speedup vs baseline: 1.1896x; 1.1896x over previous
#include <cuda_runtime.h>
#include <math.h>

#define OWN_DIM 7
#define INTR_DIM 5
#define N_HEADS 3
#define HEAD_DIM 5
#define N_INTR 256
#define HID 256
#define BATCH 16384
#define OBS_DIM 1287           // OWN_DIM + N_INTR*INTR_DIM
#define XDIM 22                // OWN_DIM + N_HEADS*HEAD_DIM
#define TR 32                  // rows per MLP block

typedef unsigned long long u64;

// transposed x buffer: [feature][row]  (1.44 MB device-global scratch)
__device__ float g_xT[XDIM * BATCH];

// ---- packed f32x2 helpers (sm_103a FFMA2 via PTX) ----
__device__ __forceinline__ u64 pack2(float lo, float hi){
    u64 r; asm("mov.b64 %0, {%1,%2};" : "=l"(r) : "f"(lo), "f"(hi)); return r;
}
__device__ __forceinline__ void unpack2(u64 v, float& lo, float& hi){
    asm("mov.b64 {%0,%1}, %2;" : "=f"(lo), "=f"(hi) : "l"(v));
}
__device__ __forceinline__ u64 ffma2(u64 a, u64 b, u64 c){
    u64 d; asm("fma.rn.f32x2 %0, %1, %2, %3;" : "=l"(d) : "l"(a), "l"(b), "l"(c)); return d;
}

// accurate tanh (~1e-6): tanh(x) = 1 - 2/(exp(2x)+1). No NaNs at +-inf.
__device__ __forceinline__ float tanh_fast(float x){
    float e = __expf(2.0f * x);
    return 1.0f - __fdividef(2.0f, e + 1.0f);
}

// ============================================================
// Kernel 1: attention.  warp-per-row, 8 warps / block.
// Items packed as f32x2 pairs: pair p = items (2p, 2p+1) of this lane.
// ============================================================
__global__ void __launch_bounds__(256, 2)
attn_kernel(const float* __restrict__ obs,
            const float* __restrict__ Wq, const float* __restrict__ bq,
            const float* __restrict__ Wk, const float* __restrict__ bk,
            const float* __restrict__ Wv, const float* __restrict__ bv,
            const float* __restrict__ v_att, const float* __restrict__ temp)
{
    __shared__ float s_obs[8][OBS_DIM + 1];
    __shared__ float s_w[316];
    const int WQ = 0, BQ = 105, WK = 120, BK = 195, WV = 210, BV = 285, VA = 300, TT = 315;

    const int tid  = threadIdx.x;
    const int w    = tid >> 5;
    const int lane = tid & 31;

    // cooperative weight staging
    if (tid < 105)      s_w[WQ + tid]        = Wq[tid];
    else if (tid < 120) s_w[BQ + tid - 105]  = bq[tid - 105];
    else if (tid < 195) s_w[WK + tid - 120]  = Wk[tid - 120];
    else if (tid < 210) s_w[BK + tid - 195]  = bk[tid - 195];
    if (tid < 75)       s_w[WV + tid]        = Wv[tid];
    else if (tid < 90)  s_w[BV + tid - 75]   = bv[tid - 75];
    else if (tid < 105) s_w[VA + tid - 90]   = v_att[tid - 90];
    if (tid == 255)     s_w[TT]              = fabsf(temp[0]);

    // coalesced row staging (one warp per row)
    const int row = blockIdx.x * 8 + w;
    const float* gobs = obs + (size_t)row * OBS_DIM;
    for (int j = lane; j < OBS_DIM; j += 32) s_obs[w][j] = gobs[j];
    __syncthreads();

    const float* R = s_obs[w];

    // each lane owns 8 items: n = lane + 32*t ; packed pairs p=(t=2p, t=2p+1)
    u64 xi2[4][5];
    unsigned padmask = 0;
    #pragma unroll
    for (int p = 0; p < 4; p++){
        float a5[5], b5[5];
        {
            const float* pa = R + OWN_DIM + 5 * (lane + 32 * (2*p));
            float s = 0.f;
            #pragma unroll
            for (int i = 0; i < 5; i++){ a5[i] = pa[i]; s += fabsf(a5[i]); }
            if (s < 1e-6f) padmask |= (1u << (2*p));
        }
        {
            const float* pb = R + OWN_DIM + 5 * (lane + 32 * (2*p+1));
            float s = 0.f;
            #pragma unroll
            for (int i = 0; i < 5; i++){ b5[i] = pb[i]; s += fabsf(b5[i]); }
            if (s < 1e-6f) padmask |= (1u << (2*p+1));
        }
        #pragma unroll
        for (int i = 0; i < 5; i++) xi2[p][i] = pack2(a5[i], b5[i]);
    }

    // -------- pass 1: scores (packed over item pairs) --------
    const float T = s_w[TT];
    u64 sc2[3][4];
    #pragma unroll
    for (int h = 0; h < 3; h++){
        float qb[5];
        #pragma unroll
        for (int d = 0; d < 5; d++){
            float a = s_w[BQ + h*5 + d] + s_w[BK + h*5 + d];   // fold bk into q
            #pragma unroll
            for (int o = 0; o < 7; o++) a += s_w[WQ + (h*5 + d)*7 + o] * R[o];
            qb[d] = a;
        }
        #pragma unroll
        for (int p = 0; p < 4; p++) sc2[h][p] = pack2(0.f, 0.f);

        #pragma unroll
        for (int d = 0; d < 5; d++){
            const int rowk = (h*5 + d)*5;
            u64 w0 = pack2(s_w[WK + rowk + 0], s_w[WK + rowk + 0]);
            u64 w1 = pack2(s_w[WK + rowk + 1], s_w[WK + rowk + 1]);
            u64 w2 = pack2(s_w[WK + rowk + 2], s_w[WK + rowk + 2]);
            u64 w3 = pack2(s_w[WK + rowk + 3], s_w[WK + rowk + 3]);
            u64 w4 = pack2(s_w[WK + rowk + 4], s_w[WK + rowk + 4]);
            u64 q2 = pack2(qb[d], qb[d]);
            float va = s_w[VA + h*5 + d];
            u64 va2 = pack2(va, va);
            #pragma unroll
            for (int p = 0; p < 4; p++){
                u64 kv = ffma2(xi2[p][0], w0, q2);
                kv = ffma2(xi2[p][1], w1, kv);
                kv = ffma2(xi2[p][2], w2, kv);
                kv = ffma2(xi2[p][3], w3, kv);
                kv = ffma2(xi2[p][4], w4, kv);
                float lo, hi; unpack2(kv, lo, hi);
                u64 e2 = pack2(tanh_fast(lo), tanh_fast(hi));
                sc2[h][p] = ffma2(e2, va2, sc2[h][p]);
            }
        }
    }

    // -------- softmax (per head, warp-wide over 256 items) --------
    float inv[3];
    #pragma unroll
    for (int h = 0; h < 3; h++){
        float s8[8];
        #pragma unroll
        for (int p = 0; p < 4; p++){
            float lo, hi; unpack2(sc2[h][p], lo, hi);
            s8[2*p]   = ((padmask >> (2*p))   & 1u) ? -INFINITY : lo * T;
            s8[2*p+1] = ((padmask >> (2*p+1)) & 1u) ? -INFINITY : hi * T;
        }
        float m = -INFINITY;
        #pragma unroll
        for (int t = 0; t < 8; t++) m = fmaxf(m, s8[t]);
        #pragma unroll
        for (int off = 16; off; off >>= 1) m = fmaxf(m, __shfl_xor_sync(0xffffffffu, m, off));
        const bool ok = (m > -INFINITY);
        float l = 0.f;
        #pragma unroll
        for (int t = 0; t < 8; t++){
            float pr = ok ? __expf(s8[t] - m) : 0.f;
            s8[t] = pr;
            l += pr;
        }
        #pragma unroll
        for (int off = 16; off; off >>= 1) l += __shfl_xor_sync(0xffffffffu, l, off);
        inv[h] = (l > 0.f) ? __fdividef(1.f, l) : 0.f;
        // repack probabilities
        #pragma unroll
        for (int p = 0; p < 4; p++) sc2[h][p] = pack2(s8[2*p], s8[2*p+1]);
    }

    // -------- pass 2: context = sum alpha * v (packed) --------
    u64 ctx2[15];
    #pragma unroll
    for (int j = 0; j < 15; j++) ctx2[j] = pack2(0.f, 0.f);
    #pragma unroll
    for (int h = 0; h < 3; h++){
        #pragma unroll
        for (int d = 0; d < 5; d++){
            const int rowv = (h*5 + d)*5;
            u64 w0 = pack2(s_w[WV + rowv + 0], s_w[WV + rowv + 0]);
            u64 w1 = pack2(s_w[WV + rowv + 1], s_w[WV + rowv + 1]);
            u64 w2 = pack2(s_w[WV + rowv + 2], s_w[WV + rowv + 2]);
            u64 w3 = pack2(s_w[WV + rowv + 3], s_w[WV + rowv + 3]);
            u64 w4 = pack2(s_w[WV + rowv + 4], s_w[WV + rowv + 4]);
            float bvv = s_w[BV + h*5 + d];
            u64 bv2 = pack2(bvv, bvv);
            u64 cacc = ctx2[h*5 + d];
            #pragma unroll
            for (int p = 0; p < 4; p++){
                u64 vv = ffma2(xi2[p][0], w0, bv2);
                vv = ffma2(xi2[p][1], w1, vv);
                vv = ffma2(xi2[p][2], w2, vv);
                vv = ffma2(xi2[p][3], w3, vv);
                vv = ffma2(xi2[p][4], w4, vv);
                cacc = ffma2(sc2[h][p], vv, cacc);
            }
            ctx2[h*5 + d] = cacc;
        }
    }

    // reduce the 15 context values: (lo+hi) * inv, then warp-sum
    float ctx[15];
    #pragma unroll
    for (int j = 0; j < 15; j++){
        float lo, hi; unpack2(ctx2[j], lo, hi);
        float c = (lo + hi) * inv[j / 5];
        #pragma unroll
        for (int off = 16; off; off >>= 1) c += __shfl_xor_sync(0xffffffffu, c, off);
        ctx[j] = c;
    }

    if (lane == 0){
        #pragma unroll
        for (int o = 0; o < 7; o++)  g_xT[o * BATCH + row]        = R[o];
        #pragma unroll
        for (int j = 0; j < 15; j++) g_xT[(7 + j) * BATCH + row]  = ctx[j];
    }
}

// ============================================================
// Kernel 2: MLP.  256 threads; thread = 2 hidden columns x 16 rows.
//   tid>>7 selects row half (rows [hi*16, hi*16+16) of the 32-row tile)
//   tid&127 -> cols c0=col, c1=col+128
// Each LDS.128 of activations now feeds 2 columns -> LDS wavefronts halved.
// ============================================================
__global__ void __launch_bounds__(256, 2)
mlp_kernel(const float* __restrict__ W1, const float* __restrict__ b1,
           const float* __restrict__ W2, const float* __restrict__ b2,
           const float* __restrict__ Wf, const float* __restrict__ bf,
           const float* __restrict__ log_std, float* __restrict__ out)
{
    extern __shared__ float sm[];
    float* xsT = sm;                       // [XDIM][TR]           704 floats
    float* h1T = sm + XDIM * TR;           // [HID][36] transposed (pad 36 => 16B-aligned rows)
    float* h2T = h1T + HID * 36;

    const int tid   = threadIdx.x;
    const int hi    = tid >> 7;            // row half
    const int col   = tid & 127;
    const int c0    = col, c1 = col + 128;
    const int rb    = hi * 16;             // local row base
    const int rbase = blockIdx.x * TR;

    // load x transposed tile (coalesced: 32 consecutive rows per feature)
    for (int idx = tid; idx < XDIM * TR; idx += 256)
        xsT[idx] = g_xT[(idx >> 5) * BATCH + rbase + (idx & 31)];
    __syncthreads();

    // ---- stage 1: h1 = lrelu(x @ W1 + b1) ----
    {
        u64 accA[8], accB[8];
        {
            const float ba = b1[c0], bb = b1[c1];
            const u64 bpa = pack2(ba, ba), bpb = pack2(bb, bb);
            #pragma unroll
            for (int q = 0; q < 8; q++){ accA[q] = bpa; accB[q] = bpb; }
        }
        #pragma unroll
        for (int i = 0; i < XDIM; i++){
            const float wa = W1[i * HID + c0];
            const float wb = W1[i * HID + c1];
            const u64 wpa = pack2(wa, wa);
            const u64 wpb = pack2(wb, wb);
            const ulonglong2* xp = (const ulonglong2*)(xsT + i * TR + rb);
            #pragma unroll
            for (int q = 0; q < 4; q++){
                ulonglong2 hh = xp[q];
                accA[2*q]   = ffma2(hh.x, wpa, accA[2*q]);
                accA[2*q+1] = ffma2(hh.y, wpa, accA[2*q+1]);
                accB[2*q]   = ffma2(hh.x, wpb, accB[2*q]);
                accB[2*q+1] = ffma2(hh.y, wpb, accB[2*q+1]);
            }
        }
        #pragma unroll
        for (int q = 0; q < 8; q++){
            float a, c; unpack2(accA[q], a, c);
            a = fmaxf(a, 0.2f * a); c = fmaxf(c, 0.2f * c);
            *(u64*)(h1T + c0 * 36 + rb + 2 * q) = pack2(a, c);
            unpack2(accB[q], a, c);
            a = fmaxf(a, 0.2f * a); c = fmaxf(c, 0.2f * c);
            *(u64*)(h1T + c1 * 36 + rb + 2 * q) = pack2(a, c);
        }
    }
    __syncthreads();

    // ---- stage 2: h2 = lrelu(h1 @ W2 + b2) ----
    {
        u64 accA[8], accB[8];
        {
            const float ba = b2[c0], bb = b2[c1];
            const u64 bpa = pack2(ba, ba), bpb = pack2(bb, bb);
            #pragma unroll
            for (int q = 0; q < 8; q++){ accA[q] = bpa; accB[q] = bpb; }
        }
        const float* w2a = W2 + c0;
        const float* w2b = W2 + c1;
        #pragma unroll 4
        for (int i = 0; i < HID; i++){
            const float wa = __ldg(w2a + i * HID);
            const float wb = __ldg(w2b + i * HID);
            const u64 wpa = pack2(wa, wa);
            const u64 wpb = pack2(wb, wb);
            const ulonglong2* hp = (const ulonglong2*)(h1T + i * 36 + rb);
            #pragma unroll
            for (int q = 0; q < 4; q++){
                ulonglong2 hh = hp[q];
                accA[2*q]   = ffma2(hh.x, wpa, accA[2*q]);
                accA[2*q+1] = ffma2(hh.y, wpa, accA[2*q+1]);
                accB[2*q]   = ffma2(hh.x, wpb, accB[2*q]);
                accB[2*q+1] = ffma2(hh.y, wpb, accB[2*q+1]);
            }
        }
        #pragma unroll
        for (int q = 0; q < 8; q++){
            float a, c; unpack2(accA[q], a, c);
            a = fmaxf(a, 0.2f * a); c = fmaxf(c, 0.2f * c);
            *(u64*)(h2T + c0 * 36 + rb + 2 * q) = pack2(a, c);
            unpack2(accB[q], a, c);
            a = fmaxf(a, 0.2f * a); c = fmaxf(c, 0.2f * c);
            *(u64*)(h2T + c1 * 36 + rb + 2 * q) = pack2(a, c);
        }
    }
    __syncthreads();

    // ---- stage 3: out = h2 @ Wf + bf ; append log_std ----
    if (tid < 64){
        const int r = tid >> 1, a = tid & 1;
        float acc = bf[a];
        #pragma unroll 8
        for (int j = 0; j < HID; j++)
            acc += h2T[j * 36 + r] * Wf[j * 2 + a];
        const int row = rbase + r;
        out[row * 4 + a]     = acc;
        out[row * 4 + 2 + a] = log_std[a];
    }
}

// ============================================================
extern "C" void kernel_launch(void* const* d_in, const int* in_sizes, int n_in,
                              void* d_out, int out_size)
{
    const float* obs     = (const float*)d_in[0];
    const float* Wq      = (const float*)d_in[1];
    const float* bq      = (const float*)d_in[2];
    const float* Wk      = (const float*)d_in[3];
    const float* bk      = (const float*)d_in[4];
    const float* Wv      = (const float*)d_in[5];
    const float* bv      = (const float*)d_in[6];
    const float* v_att   = (const float*)d_in[7];
    const float* temp    = (const float*)d_in[8];
    const float* W1      = (const float*)d_in[9];
    const float* b1      = (const float*)d_in[10];
    const float* W2      = (const float*)d_in[11];
    const float* b2      = (const float*)d_in[12];
    const float* Wf      = (const float*)d_in[13];
    const float* bf      = (const float*)d_in[14];
    const float* log_std = (const float*)d_in[15];

    attn_kernel<<<BATCH / 8, 256>>>(obs, Wq, bq, Wk, bk, Wv, bv, v_att, temp);

    const size_t smem = (size_t)(XDIM * TR + 2 * HID * 36) * sizeof(float);  // 76544 B
    cudaFuncSetAttribute(mlp_kernel, cudaFuncAttributeMaxDynamicSharedMemorySize, (int)smem);
    mlp_kernel<<<BATCH / TR, 256, smem>>>(W1, b1, W2, b2, Wf, bf, log_std, (float*)d_out);
}